// round 3
// baseline (speedup 1.0000x reference)
#include <cuda_runtime.h>
#include <math.h>

typedef unsigned long long u64;
#define FULLMASK 0xffffffffu

// ---- f32x2 packed-math helpers (sm_100+ PTX) ----
__device__ __forceinline__ u64 pk2(float lo, float hi) {
    u64 r; asm("mov.b64 %0, {%1,%2};" : "=l"(r) : "f"(lo), "f"(hi)); return r;
}
__device__ __forceinline__ void upk2(u64 v, float &lo, float &hi) {
    asm("mov.b64 {%0,%1}, %2;" : "=f"(lo), "=f"(hi) : "l"(v));
}
__device__ __forceinline__ void ffma2(u64 &d, u64 a, u64 b) {
    asm("fma.rn.f32x2 %0, %1, %2, %0;" : "+l"(d) : "l"(a), "l"(b));
}
__device__ __forceinline__ u64 mul2(u64 a, u64 b) {
    u64 r; asm("mul.rn.f32x2 %0, %1, %2;" : "=l"(r) : "l"(a), "l"(b)); return r;
}
__device__ __forceinline__ void lds2(u64 &a, u64 &b, unsigned addr) {
    asm volatile("ld.shared.v2.u64 {%0,%1}, [%2];" : "=l"(a), "=l"(b) : "r"(addr));
}
__device__ __forceinline__ void sts2(unsigned addr, u64 a, u64 b) {
    asm volatile("st.shared.v2.u64 [%0], {%1,%2};" :: "r"(addr), "l"(a), "l"(b) : "memory");
}
__device__ __forceinline__ void cpasync16(unsigned saddr, const void* g) {
    asm volatile("cp.async.cg.shared.global [%0], [%1], 16;" :: "r"(saddr), "l"(g) : "memory");
}

// ---- geometry ----
static constexpr int ROWS     = 56;    // batch rows per CTA
static constexpr int THREADS  = 224;   // 4 threads per row
static constexpr int G_I      = 160;   // smem float stride per i   (mod32 = 0, uniform)
static constexpr int G_V      = 80;    // smem float stride per phys (mod32 = 16 -> conflict-free)
static constexpr int GBUF     = 64 * G_I;              // 10240 floats per site buffer
static constexpr int ENV_OFF  = 2 * GBUF;              // 20480
static constexpr int ENV_STR  = 72;                    // env row stride (floats)
static constexpr int CFG_OFF  = ENV_OFF + ROWS * ENV_STR;   // 24512
static constexpr int SMEM_FLOATS = CFG_OFF + ROWS * 8;      // 24960
static constexpr int SMEM_BYTES  = SMEM_FLOATS * 4;         // 99840 B

__global__ void __launch_bounds__(THREADS, 1)
mps_kernel(const int* __restrict__ cfg, const float* __restrict__ left,
           const float* __restrict__ bulk, const float* __restrict__ right,
           float* __restrict__ out, int B, int nbulk)
{
    extern __shared__ float smem[];
    const unsigned sbase = (unsigned)__cvta_generic_to_shared(smem);
    const int tid  = threadIdx.x;
    const int lane = tid & 31;
    const int warp = tid >> 5;
    const int s    = tid & 3;        // sub-lane within row group
    const int lr   = tid >> 2;       // local row 0..55
    const int grow = blockIdx.x * ROWS + lr;
    unsigned* cfgb = (unsigned*)(smem + CFG_OFF);

    // ---- pack per-row configuration bits (256 sites -> 8 words/row) ----
    for (int g = 0; g < 8; ++g) {
        int lrow = warp * 8 + g;
        int gr   = blockIdx.x * ROWS + lrow;
        #pragma unroll
        for (int wo = 0; wo < 8; ++wo) {
            int vv = 0;
            if (gr < B) vv = cfg[(size_t)gr * 256 + wo * 32 + lane] & 1;
            unsigned word = __ballot_sync(FULLMASK, vv);
            if (lane == 0) cfgb[lrow * 8 + wo] = word;
        }
    }
    __syncthreads();

    // ---- prefetch helper: bulk site -> padded smem buffer via cp.async ----
    auto prefetch = [&](int bulkIdx, int bi) {
        const float4* src = (const float4*)bulk + (size_t)bulkIdx * 2048;
        unsigned dbase = sbase + (unsigned)(bi * GBUF * 4);
        #pragma unroll
        for (int q = 0; q < 10; ++q) {
            int idx = tid + THREADS * q;
            if (idx < 2048) {
                unsigned off = (unsigned)((idx >> 5) * G_I + ((idx >> 4) & 1) * G_V
                                          + ((idx & 15) << 2)) << 2;
                cpasync16(dbase + off, src + idx);
            }
        }
        asm volatile("cp.async.commit_group;" ::: "memory");
    };

    prefetch(0, 0);   // site 1 -> buffer 0

    const unsigned envw = sbase + (unsigned)((ENV_OFF + lr * ENV_STR + 4 * s) * 4);
    const float*  envrow = smem + ENV_OFF + lr * ENV_STR;
    float ls = 0.f;

    // ---- init env from `left`, rescale, store to smem ----
    {
        int v0 = cfgb[lr * 8] & 1;
        float a[16];
        #pragma unroll
        for (int k = 0; k < 4; ++k)
            #pragma unroll
            for (int c = 0; c < 4; ++c)
                a[k * 4 + c] = left[v0 * 64 + 4 * s + 16 * k + c];
        float m = 0.f;
        #pragma unroll
        for (int x = 0; x < 16; ++x) m = fmaxf(m, fabsf(a[x]));
        m = fmaxf(m, __shfl_xor_sync(FULLMASK, m, 1));
        m = fmaxf(m, __shfl_xor_sync(FULLMASK, m, 2));
        m = fmaxf(m, 1e-30f);
        ls += logf(m);
        float inv = 1.0f / m;
        #pragma unroll
        for (int k = 0; k < 4; ++k)
            sts2(envw + 64u * k, pk2(a[4*k]*inv, a[4*k+1]*inv),
                                 pk2(a[4*k+2]*inv, a[4*k+3]*inv));
    }

    // ---- main chain over bulk sites ----
    #pragma unroll 1
    for (int tt = 1; tt <= nbulk; ++tt) {
        asm volatile("cp.async.wait_group 0;" ::: "memory");
        __syncthreads();
        if (tt < nbulk) prefetch(tt, tt & 1);

        const int v = (cfgb[lr * 8 + (tt >> 5)] >> (tt & 31)) & 1;
        const unsigned gb = sbase + (unsigned)((((tt - 1) & 1) * GBUF + v * G_V + 4 * s) * 4);

        u64 acc[8];
        #pragma unroll
        for (int p = 0; p < 8; ++p) acc[p] = 0ull;

        #define MSTEP(EV, II) { u64 ee = pk2((EV), (EV));                      \
            unsigned ga = gb + (unsigned)((II) * 640);                         \
            u64 g0, g1;                                                        \
            lds2(g0, g1, ga      ); ffma2(acc[0], ee, g0); ffma2(acc[1], ee, g1); \
            lds2(g0, g1, ga +  64u); ffma2(acc[2], ee, g0); ffma2(acc[3], ee, g1); \
            lds2(g0, g1, ga + 128u); ffma2(acc[4], ee, g0); ffma2(acc[5], ee, g1); \
            lds2(g0, g1, ga + 192u); ffma2(acc[6], ee, g0); ffma2(acc[7], ee, g1); }

        #pragma unroll
        for (int iv = 0; iv < 16; ++iv) {
            float4 e4 = *(const float4*)(envrow + 4 * iv);
            MSTEP(e4.x, 4 * iv + 0)
            MSTEP(e4.y, 4 * iv + 1)
            MSTEP(e4.z, 4 * iv + 2)
            MSTEP(e4.w, 4 * iv + 3)
        }
        #undef MSTEP

        // ---- rescale: group max, log accumulate, store scaled env ----
        float xf[16];
        #pragma unroll
        for (int p = 0; p < 8; ++p) upk2(acc[p], xf[2 * p], xf[2 * p + 1]);
        float m = 0.f;
        #pragma unroll
        for (int x = 0; x < 16; ++x) m = fmaxf(m, fabsf(xf[x]));
        m = fmaxf(m, __shfl_xor_sync(FULLMASK, m, 1));
        m = fmaxf(m, __shfl_xor_sync(FULLMASK, m, 2));
        m = fmaxf(m, 1e-30f);
        ls += logf(m);
        float inv = 1.0f / m;
        u64 inv2 = pk2(inv, inv);
        #pragma unroll
        for (int k = 0; k < 4; ++k)
            sts2(envw + 64u * k, mul2(acc[2 * k], inv2), mul2(acc[2 * k + 1], inv2));
    }

    // ---- final site: contract with `right`, emit log amplitude^2 ----
    {
        int lastbit = nbulk + 1;                       // site index 255
        int v = (cfgb[lr * 8 + (lastbit >> 5)] >> (lastbit & 31)) & 1;
        float p = 0.f;
        #pragma unroll
        for (int k = 0; k < 4; ++k) {
            float4 ev = *(const float4*)(envrow + 4 * s + 16 * k);
            int i0 = 4 * s + 16 * k;
            p += ev.x * right[(i0 + 0) * 2 + v];
            p += ev.y * right[(i0 + 1) * 2 + v];
            p += ev.z * right[(i0 + 2) * 2 + v];
            p += ev.w * right[(i0 + 3) * 2 + v];
        }
        p += __shfl_xor_sync(FULLMASK, p, 1);
        p += __shfl_xor_sync(FULLMASK, p, 2);
        if (s == 0 && grow < B) {
            float m2 = fmaxf(fabsf(p), 1e-30f);
            float pr = p / m2;
            float ab = fmaxf(pr * pr, 1e-30f);
            out[grow] = logf(ab) + 2.0f * (ls + logf(m2));
        }
    }
}

extern "C" void kernel_launch(void* const* d_in, const int* in_sizes, int n_in,
                              void* d_out, int out_size)
{
    const int*   cfg   = (const int*)d_in[0];
    const float* left  = (const float*)d_in[1];
    const float* bulk  = (const float*)d_in[2];
    const float* right = (const float*)d_in[3];
    float* out = (float*)d_out;

    int B     = in_sizes[0] / 256;          // 8192
    int nbulk = in_sizes[2] / (64 * 2 * 64); // 254
    int ncta  = (B + ROWS - 1) / ROWS;       // 147

    cudaFuncSetAttribute(mps_kernel, cudaFuncAttributeMaxDynamicSharedMemorySize, SMEM_BYTES);
    mps_kernel<<<ncta, THREADS, SMEM_BYTES>>>(cfg, left, bulk, right, out, B, nbulk);
}